// round 4
// baseline (speedup 1.0000x reference)
#include <cuda_runtime.h>

// ProbsNet fused single-kernel, single-wave persistent grid.
//   out = sum_i c0[i]*tmp0[i] + c1[i]*tmp1[i]
//   tmpX[i] = sum_d sigmoid(pB*(pBEV*BEV + STX[i,d])) * WX[i,d]
// 176 MB fp32 read-once streaming -> HBM-bound. Tiles of 1024 float4 align
// to rows (32768 float4/row) so coefficient is scalar per tile.

#define D        131072
#define NROWS    84
#define VPR      (D / 4)              // 32768 float4 per row
#define NVEC     (NROWS * VPR)        // 2752512 float4 per (ST,W) pair
#define BLOCK    256
#define UNROLL   4
#define TILE     (BLOCK * UNROLL)     // 1024 float4 per tile
#define TILES1   (NVEC / TILE)        // 2688 tiles per pair (exact)
#define TILES    (2 * TILES1)         // 5376
#define GRID     1036                 // 148 SMs * 7 blocks @36regs = ONE wave

__device__ float        g_part[GRID];
__device__ unsigned int g_sem = 0;    // self-resetting (graph-replay safe)

// Entry e (0..83) of calc_probs(logits), flattened (4,21) layout.
__device__ __forceinline__ float probs_entry(const float* __restrict__ logits, int e) {
    float e0 = __expf(logits[0]);
    float e1 = __expf(logits[1]);
    float e2 = __expf(logits[2]);
    float e3 = __expf(logits[3]);
    float inv = __fdividef(1.0f, e0 + e1 + e2 + e3);
    float p[4] = {e0 * inv, e1 * inv, e2 * inv, e3 * inv};
    int i = e / 21;
    int r = e - i * 21;
    float v = p[i];
    if (r > 0) {
        int q  = r - 1;
        int j  = q / 5;
        int rr = q - j * 5;
        v *= p[j];
        if (rr > 0) v *= p[rr - 1];
    }
    return v;
}

// sigmoid(pB*(bev+s)) = 1 / (1 + exp2(a*s + b)),  a = -pB*log2e, b = a*bev
__device__ __forceinline__ float sig_dot4(float4 s4, float4 w4, float a, float b) {
    float t;
    t  = w4.x * __frcp_rn(1.0f + exp2f(fmaf(a, s4.x, b)));
    t += w4.y * __frcp_rn(1.0f + exp2f(fmaf(a, s4.y, b)));
    t += w4.z * __frcp_rn(1.0f + exp2f(fmaf(a, s4.z, b)));
    t += w4.w * __frcp_rn(1.0f + exp2f(fmaf(a, s4.w, b)));
    return t;
}

__global__ void __launch_bounds__(BLOCK)
fused_kernel(const float* __restrict__ BEV,
             const float* __restrict__ ST0, const float* __restrict__ W0,
             const float* __restrict__ ST1, const float* __restrict__ W1,
             const float* __restrict__ probs0, const float* __restrict__ probs1,
             const float* __restrict__ probs2, const float* __restrict__ probs3,
             const float* __restrict__ probs4,
             const float* __restrict__ pBEV, const float* __restrict__ pB,
             float* __restrict__ out) {
    __shared__ float sc[2 * NROWS];
    const int tid = threadIdx.x;

    if (tid < NROWS) {
        sc[tid] = 0.2f * probs_entry(probs0, tid);
        float c1 = probs_entry(probs1, tid) + probs_entry(probs2, tid)
                 + probs_entry(probs3, tid) + probs_entry(probs4, tid);
        sc[NROWS + tid] = 0.2f * c1;
    }
    __syncthreads();

    const float scale = pB[0];
    const float a = -scale * 1.4426950408889634f;   // -pB * log2(e)
    const float b = a * (pBEV[0] * BEV[0]);

    const float4* __restrict__ st0 = (const float4*)ST0;
    const float4* __restrict__ w0  = (const float4*)W0;
    const float4* __restrict__ st1 = (const float4*)ST1;
    const float4* __restrict__ w1  = (const float4*)W1;

    float acc = 0.0f;

    // Persistent single-wave grid-stride over tiles. One coefficient/tile.
    for (int t = blockIdx.x; t < TILES; t += GRID) {
        const bool second = (t >= TILES1);
        const int  tt     = second ? (t - TILES1) : t;
        const int  v0     = tt * TILE;
        const float4* __restrict__ st = second ? st1 : st0;
        const float4* __restrict__ w  = second ? w1  : w0;
        const float c = sc[(second ? NROWS : 0) + (v0 >> 15)];

        // 8 front-batched streaming LDG.128 (read-once: evict-first)
        float4 s[UNROLL], ww[UNROLL];
        #pragma unroll
        for (int u = 0; u < UNROLL; u++) {
            int v = v0 + u * BLOCK + tid;
            s[u]  = __ldcs(&st[v]);
            ww[u] = __ldcs(&w[v]);
        }

        float tsum = 0.0f;
        #pragma unroll
        for (int u = 0; u < UNROLL; u++)
            tsum += sig_dot4(s[u], ww[u], a, b);

        acc = fmaf(c, tsum, acc);
    }

    // --- block reduce (fixed tree, deterministic) ---
    for (int off = 16; off > 0; off >>= 1)
        acc += __shfl_down_sync(0xFFFFFFFFu, acc, off);

    __shared__ float sm[BLOCK / 32];
    int lane = tid & 31;
    int wid  = tid >> 5;
    if (lane == 0) sm[wid] = acc;
    __syncthreads();
    if (wid == 0) {
        float bsum = (lane < BLOCK / 32) ? sm[lane] : 0.0f;
        for (int off = 4; off > 0; off >>= 1)
            bsum += __shfl_down_sync(0xFFFFFFFFu, bsum, off);
        if (lane == 0) g_part[blockIdx.x] = bsum;
    }

    // --- last block folds partials (deterministic fixed-order) ---
    __shared__ bool is_last;
    __threadfence();
    if (tid == 0)
        is_last = (atomicAdd(&g_sem, 1u) == GRID - 1);
    __syncthreads();

    if (is_last) {
        __threadfence();
        float a2 = 0.0f;
        for (int i = tid; i < GRID; i += BLOCK)
            a2 += g_part[i];
        for (int off = 16; off > 0; off >>= 1)
            a2 += __shfl_down_sync(0xFFFFFFFFu, a2, off);
        if (lane == 0) sm[wid] = a2;
        __syncthreads();
        if (tid == 0) {
            float s = 0.0f;
            #pragma unroll
            for (int i = 0; i < BLOCK / 32; i++) s += sm[i];
            out[0] = s;
            g_sem  = 0;
        }
    }
}

// Input order: BEV, ST0, Weight0, ST1, Weight1, Problem, probs0..4, pBEV, pB
extern "C" void kernel_launch(void* const* d_in, const int* in_sizes, int n_in,
                              void* d_out, int out_size) {
    const float* BEV    = (const float*)d_in[0];
    const float* ST0    = (const float*)d_in[1];
    const float* W0     = (const float*)d_in[2];
    const float* ST1    = (const float*)d_in[3];
    const float* W1     = (const float*)d_in[4];
    const float* probs0 = (const float*)d_in[6];
    const float* probs1 = (const float*)d_in[7];
    const float* probs2 = (const float*)d_in[8];
    const float* probs3 = (const float*)d_in[9];
    const float* probs4 = (const float*)d_in[10];
    const float* pBEV   = (const float*)d_in[11];
    const float* pB     = (const float*)d_in[12];

    fused_kernel<<<GRID, BLOCK>>>(BEV, ST0, W0, ST1, W1,
                                  probs0, probs1, probs2, probs3, probs4,
                                  pBEV, pB, (float*)d_out);
}

// round 5
// speedup vs baseline: 1.1016x; 1.1016x over previous
#include <cuda_runtime.h>

// ProbsNet fused single-kernel, true single-wave persistent grid.
//   out = sum_i c0[i]*tmp0[i] + c1[i]*tmp1[i]
//   tmpX[i] = sum_d sigmoid(pB*(pBEV*BEV + STX[i,d])) * WX[i,d]
// 176 MB fp32 read-once streaming -> HBM-bound. Tiles of 1024 float4 align
// to rows (32768 float4/row) so the coefficient is scalar per tile.

#define D        131072
#define NROWS    84
#define VPR      (D / 4)              // 32768 float4 per row
#define NVEC     (NROWS * VPR)        // 2752512 float4 per (ST,W) pair
#define BLOCK    256
#define UNROLL   4
#define TILE     (BLOCK * UNROLL)     // 1024 float4 per tile
#define TILES1   (NVEC / TILE)        // 2688 tiles per pair (exact)
#define TILES    (2 * TILES1)         // 5376
#define GRID     888                  // 148 SMs * 6 blocks @40regs = ONE wave

__device__ float        g_part[GRID];
__device__ unsigned int g_sem = 0;    // self-resetting (graph-replay safe)

// Entry e (0..83) of calc_probs(logits), flattened (4,21) layout.
__device__ __forceinline__ float probs_entry(const float* __restrict__ logits, int e) {
    float e0 = __expf(logits[0]);
    float e1 = __expf(logits[1]);
    float e2 = __expf(logits[2]);
    float e3 = __expf(logits[3]);
    float inv = __fdividef(1.0f, e0 + e1 + e2 + e3);
    float p[4] = {e0 * inv, e1 * inv, e2 * inv, e3 * inv};
    int i = e / 21;
    int r = e - i * 21;
    float v = p[i];
    if (r > 0) {
        int q  = r - 1;
        int j  = q / 5;
        int rr = q - j * 5;
        v *= p[j];
        if (rr > 0) v *= p[rr - 1];
    }
    return v;
}

// sigmoid(pB*(bev+s)) = 1/(1+exp2(a*s+b)), a=-pB*log2e, b=a*bev.
// __fdividef(1,x) -> MUFU.RCP (fast path), exp2f(fmaf) -> FFMA+MUFU.EX2.
__device__ __forceinline__ float sig_dot4(float4 s4, float4 w4, float a, float b) {
    float t;
    t  = w4.x * __fdividef(1.0f, 1.0f + exp2f(fmaf(a, s4.x, b)));
    t += w4.y * __fdividef(1.0f, 1.0f + exp2f(fmaf(a, s4.y, b)));
    t += w4.z * __fdividef(1.0f, 1.0f + exp2f(fmaf(a, s4.z, b)));
    t += w4.w * __fdividef(1.0f, 1.0f + exp2f(fmaf(a, s4.w, b)));
    return t;
}

__global__ void __launch_bounds__(BLOCK, 6)
fused_kernel(const float* __restrict__ BEV,
             const float* __restrict__ ST0, const float* __restrict__ W0,
             const float* __restrict__ ST1, const float* __restrict__ W1,
             const float* __restrict__ probs0, const float* __restrict__ probs1,
             const float* __restrict__ probs2, const float* __restrict__ probs3,
             const float* __restrict__ probs4,
             const float* __restrict__ pBEV, const float* __restrict__ pB,
             float* __restrict__ out) {
    __shared__ float sc[2 * NROWS];
    const int tid = threadIdx.x;

    if (tid < NROWS) {
        sc[tid] = 0.2f * probs_entry(probs0, tid);
        float c1 = probs_entry(probs1, tid) + probs_entry(probs2, tid)
                 + probs_entry(probs3, tid) + probs_entry(probs4, tid);
        sc[NROWS + tid] = 0.2f * c1;
    }
    __syncthreads();

    const float a = -pB[0] * 1.4426950408889634f;   // -pB * log2(e)
    const float b = a * (pBEV[0] * BEV[0]);

    const float4* __restrict__ st0 = (const float4*)ST0;
    const float4* __restrict__ w0  = (const float4*)W0;
    const float4* __restrict__ st1 = (const float4*)ST1;
    const float4* __restrict__ w1  = (const float4*)W1;

    float acc = 0.0f;

    // Persistent single-wave grid-stride over tiles. One coefficient/tile.
    for (int t = blockIdx.x; t < TILES; t += GRID) {
        const bool second = (t >= TILES1);
        const int  tt     = second ? (t - TILES1) : t;
        const int  v0     = tt * TILE;
        const float4* __restrict__ st = second ? st1 : st0;
        const float4* __restrict__ w  = second ? w1  : w0;
        const float c = sc[(second ? NROWS : 0) + (v0 >> 15)];

        // 8 front-batched streaming LDG.128 (read-once: evict-first)
        float4 s[UNROLL], ww[UNROLL];
        #pragma unroll
        for (int u = 0; u < UNROLL; u++) {
            int v = v0 + u * BLOCK + tid;
            s[u]  = __ldcs(&st[v]);
            ww[u] = __ldcs(&w[v]);
        }

        float tsum = 0.0f;
        #pragma unroll
        for (int u = 0; u < UNROLL; u++)
            tsum += sig_dot4(s[u], ww[u], a, b);

        acc = fmaf(c, tsum, acc);
    }

    // --- block reduce (fixed tree, deterministic) ---
    for (int off = 16; off > 0; off >>= 1)
        acc += __shfl_down_sync(0xFFFFFFFFu, acc, off);

    __shared__ float sm[BLOCK / 32];
    int lane = tid & 31;
    int wid  = tid >> 5;
    if (lane == 0) sm[wid] = acc;
    __syncthreads();
    if (wid == 0) {
        float bsum = (lane < BLOCK / 32) ? sm[lane] : 0.0f;
        for (int off = 4; off > 0; off >>= 1)
            bsum += __shfl_down_sync(0xFFFFFFFFu, bsum, off);
        if (lane == 0) g_part[blockIdx.x] = bsum;
    }

    // --- last block folds partials (deterministic fixed-order) ---
    __shared__ bool is_last;
    __threadfence();
    if (tid == 0)
        is_last = (atomicAdd(&g_sem, 1u) == GRID - 1);
    __syncthreads();

    if (is_last) {
        __threadfence();
        float a2 = 0.0f;
        for (int i = tid; i < GRID; i += BLOCK)
            a2 += g_part[i];
        for (int off = 16; off > 0; off >>= 1)
            a2 += __shfl_down_sync(0xFFFFFFFFu, a2, off);
        if (lane == 0) sm[wid] = a2;
        __syncthreads();
        if (tid == 0) {
            float s = 0.0f;
            #pragma unroll
            for (int i = 0; i < BLOCK / 32; i++) s += sm[i];
            out[0] = s;
            g_sem  = 0;
        }
    }
}

// Input order: BEV, ST0, Weight0, ST1, Weight1, Problem, probs0..4, pBEV, pB
extern "C" void kernel_launch(void* const* d_in, const int* in_sizes, int n_in,
                              void* d_out, int out_size) {
    const float* BEV    = (const float*)d_in[0];
    const float* ST0    = (const float*)d_in[1];
    const float* W0     = (const float*)d_in[2];
    const float* ST1    = (const float*)d_in[3];
    const float* W1     = (const float*)d_in[4];
    const float* probs0 = (const float*)d_in[6];
    const float* probs1 = (const float*)d_in[7];
    const float* probs2 = (const float*)d_in[8];
    const float* probs3 = (const float*)d_in[9];
    const float* probs4 = (const float*)d_in[10];
    const float* pBEV   = (const float*)d_in[11];
    const float* pB     = (const float*)d_in[12];

    fused_kernel<<<GRID, BLOCK>>>(BEV, ST0, W0, ST1, W1,
                                  probs0, probs1, probs2, probs3, probs4,
                                  pBEV, pB, (float*)d_out);
}

// round 6
// speedup vs baseline: 1.1790x; 1.0703x over previous
#include <cuda_runtime.h>

// ProbsNet fused single-kernel, software-pipelined (register double-buffer).
//   out = sum_i c0[i]*tmp0[i] + c1[i]*tmp1[i]
//   tmpX[i] = sum_d sigmoid(pB*(pBEV*BEV + STX[i,d])) * WX[i,d]
// 176 MB fp32 read-once streaming -> HBM-bound. Key fix vs R5: prefetch the
// next tile's 4 LDG.128 BEFORE computing the current tile, so loads are in
// flight during the MUFU-heavy sigmoid window (R5 duty cycle ~58%).

#define D        131072
#define NROWS    84
#define VPR      (D / 4)              // 32768 float4 per row
#define NVEC     (NROWS * VPR)        // 2752512 float4 per (ST,W) pair
#define BLOCK    256
#define UNROLL   2
#define TILE     (BLOCK * UNROLL)     // 512 float4 per tile
#define TILES1   (NVEC / TILE)        // 5376 tiles per pair (exact, 64/row)
#define TILES    (2 * TILES1)         // 10752
#define GRID     592                  // 148 SMs * 4 blocks

__device__ float        g_part[GRID];
__device__ unsigned int g_sem = 0;    // self-resetting (graph-replay safe)

// Entry e (0..83) of calc_probs(logits), flattened (4,21) layout.
__device__ __forceinline__ float probs_entry(const float* __restrict__ logits, int e) {
    float e0 = __expf(logits[0]);
    float e1 = __expf(logits[1]);
    float e2 = __expf(logits[2]);
    float e3 = __expf(logits[3]);
    float inv = __fdividef(1.0f, e0 + e1 + e2 + e3);
    float p[4] = {e0 * inv, e1 * inv, e2 * inv, e3 * inv};
    int i = e / 21;
    int r = e - i * 21;
    float v = p[i];
    if (r > 0) {
        int q  = r - 1;
        int j  = q / 5;
        int rr = q - j * 5;
        v *= p[j];
        if (rr > 0) v *= p[rr - 1];
    }
    return v;
}

// sigmoid(pB*(bev+s)) = 1/(1+exp2(a*s+b)), a=-pB*log2e, b=a*bev.
__device__ __forceinline__ float sig_dot4(float4 s4, float4 w4, float a, float b) {
    float t;
    t  = w4.x * __fdividef(1.0f, 1.0f + exp2f(fmaf(a, s4.x, b)));
    t += w4.y * __fdividef(1.0f, 1.0f + exp2f(fmaf(a, s4.y, b)));
    t += w4.z * __fdividef(1.0f, 1.0f + exp2f(fmaf(a, s4.z, b)));
    t += w4.w * __fdividef(1.0f, 1.0f + exp2f(fmaf(a, s4.w, b)));
    return t;
}

struct TileRegs {
    float4 s0, s1, w0, w1;
    float  c;
};

__device__ __forceinline__ void load_tile(
        TileRegs& r, int t, int tid,
        const float4* __restrict__ st0, const float4* __restrict__ w0,
        const float4* __restrict__ st1, const float4* __restrict__ w1,
        const float* __restrict__ sc) {
    const bool second = (t >= TILES1);
    const int  ti     = second ? (t - TILES1) : t;
    const int  v0     = ti * TILE;
    const float4* __restrict__ st = second ? st1 : st0;
    const float4* __restrict__ w  = second ? w1  : w0;
    r.c  = sc[(second ? NROWS : 0) + (v0 >> 15)];
    r.s0 = st[v0 + tid];
    r.s1 = st[v0 + BLOCK + tid];
    r.w0 = w[v0 + tid];
    r.w1 = w[v0 + BLOCK + tid];
}

__device__ __forceinline__ float compute_tile(const TileRegs& r, float a, float b) {
    return r.c * (sig_dot4(r.s0, r.w0, a, b) + sig_dot4(r.s1, r.w1, a, b));
}

__global__ void __launch_bounds__(BLOCK)
fused_kernel(const float* __restrict__ BEV,
             const float* __restrict__ ST0, const float* __restrict__ W0,
             const float* __restrict__ ST1, const float* __restrict__ W1,
             const float* __restrict__ probs0, const float* __restrict__ probs1,
             const float* __restrict__ probs2, const float* __restrict__ probs3,
             const float* __restrict__ probs4,
             const float* __restrict__ pBEV, const float* __restrict__ pB,
             float* __restrict__ out) {
    __shared__ float sc[2 * NROWS];
    const int tid = threadIdx.x;

    if (tid < NROWS) {
        sc[tid] = 0.2f * probs_entry(probs0, tid);
        float c1 = probs_entry(probs1, tid) + probs_entry(probs2, tid)
                 + probs_entry(probs3, tid) + probs_entry(probs4, tid);
        sc[NROWS + tid] = 0.2f * c1;
    }
    __syncthreads();

    const float a = -pB[0] * 1.4426950408889634f;   // -pB * log2(e)
    const float b = a * (pBEV[0] * BEV[0]);

    const float4* __restrict__ st0 = (const float4*)ST0;
    const float4* __restrict__ w0  = (const float4*)W0;
    const float4* __restrict__ st1 = (const float4*)ST1;
    const float4* __restrict__ w1  = (const float4*)W1;

    float acc = 0.0f;

    // --- 2-phase software pipeline: prefetch t+GRID, compute t ---
    TileRegs bufA, bufB;
    int t = blockIdx.x;                       // GRID < TILES always
    load_tile(bufA, t, tid, st0, w0, st1, w1, sc);

    while (true) {
        int tn = t + GRID;
        bool vn = (tn < TILES);
        if (vn) load_tile(bufB, tn, tid, st0, w0, st1, w1, sc);
        acc += compute_tile(bufA, a, b);
        if (!vn) break;

        int tnn = tn + GRID;
        bool vnn = (tnn < TILES);
        if (vnn) load_tile(bufA, tnn, tid, st0, w0, st1, w1, sc);
        acc += compute_tile(bufB, a, b);
        if (!vnn) break;
        t = tnn;
    }

    // --- block reduce (fixed tree, deterministic) ---
    for (int off = 16; off > 0; off >>= 1)
        acc += __shfl_down_sync(0xFFFFFFFFu, acc, off);

    __shared__ float sm[BLOCK / 32];
    int lane = tid & 31;
    int wid  = tid >> 5;
    if (lane == 0) sm[wid] = acc;
    __syncthreads();
    if (wid == 0) {
        float bsum = (lane < BLOCK / 32) ? sm[lane] : 0.0f;
        for (int off = 4; off > 0; off >>= 1)
            bsum += __shfl_down_sync(0xFFFFFFFFu, bsum, off);
        if (lane == 0) g_part[blockIdx.x] = bsum;
    }

    // --- last block folds partials (deterministic fixed-order) ---
    __shared__ bool is_last;
    __threadfence();
    if (tid == 0)
        is_last = (atomicAdd(&g_sem, 1u) == GRID - 1);
    __syncthreads();

    if (is_last) {
        __threadfence();
        float a2 = 0.0f;
        for (int i = tid; i < GRID; i += BLOCK)
            a2 += g_part[i];
        for (int off = 16; off > 0; off >>= 1)
            a2 += __shfl_down_sync(0xFFFFFFFFu, a2, off);
        if (lane == 0) sm[wid] = a2;
        __syncthreads();
        if (tid == 0) {
            float s = 0.0f;
            #pragma unroll
            for (int i = 0; i < BLOCK / 32; i++) s += sm[i];
            out[0] = s;
            g_sem  = 0;
        }
    }
}

// Input order: BEV, ST0, Weight0, ST1, Weight1, Problem, probs0..4, pBEV, pB
extern "C" void kernel_launch(void* const* d_in, const int* in_sizes, int n_in,
                              void* d_out, int out_size) {
    const float* BEV    = (const float*)d_in[0];
    const float* ST0    = (const float*)d_in[1];
    const float* W0     = (const float*)d_in[2];
    const float* ST1    = (const float*)d_in[3];
    const float* W1     = (const float*)d_in[4];
    const float* probs0 = (const float*)d_in[6];
    const float* probs1 = (const float*)d_in[7];
    const float* probs2 = (const float*)d_in[8];
    const float* probs3 = (const float*)d_in[9];
    const float* probs4 = (const float*)d_in[10];
    const float* pBEV   = (const float*)d_in[11];
    const float* pB     = (const float*)d_in[12];

    fused_kernel<<<GRID, BLOCK>>>(BEV, ST0, W0, ST1, W1,
                                  probs0, probs1, probs2, probs3, probs4,
                                  pBEV, pB, (float*)d_out);
}